// round 14
// baseline (speedup 1.0000x reference)
#include <cuda_runtime.h>

#define TB        32
#define NTHREADS  128
#define OBS       464

typedef unsigned long long ull;

// ---------- f32x2 helpers ----------
__device__ __forceinline__ ull pk2(float lo, float hi) {
    ull r; asm("mov.b64 %0, {%1, %2};" : "=l"(r) : "f"(lo), "f"(hi)); return r;
}
__device__ __forceinline__ float2 upk2(ull v) {
    float2 f; asm("mov.b64 {%0, %1}, %2;" : "=f"(f.x), "=f"(f.y) : "l"(v)); return f;
}
__device__ __forceinline__ void fma2(ull& d, ull a, ull b) {
    asm("fma.rn.f32x2 %0, %1, %2, %0;" : "+l"(d) : "l"(a), "l"(b));
}

// exact-ish tanh: 1 - 2/(exp(2x)+1), ~1e-6 rel err (2 MUFU ops)
__device__ __forceinline__ float ftanh(float x) {
    float e = __expf(x + x);
    return 1.0f - __fdividef(2.0f, e + 1.0f);
}
// HW tanh (1 MUFU op) — attention embeddings only
__device__ __forceinline__ float ftanh_fast(float x) {
    float y; asm("tanh.approx.f32 %0, %1;" : "=f"(y) : "f"(x)); return y;
}

// ---------- cp.async ----------
__device__ __forceinline__ void cpa16(void* s, const void* g) {
    unsigned sa = (unsigned)__cvta_generic_to_shared(s);
    asm volatile("cp.async.cg.shared.global [%0], [%1], 16;" :: "r"(sa), "l"(g));
}
#define CPCOMMIT() asm volatile("cp.async.commit_group;")
#define CPWAIT0()  asm volatile("cp.async.wait_group 0;")

// prefetch one 8x256 W chunk (2048 floats) into smem (128 threads: 4 x 16B each)
__device__ __forceinline__ void pf8(float* dst, const float* src, int tid) {
#pragma unroll
    for (int i = 0; i < 4; ++i)
        cpa16(dst + (i * 128 + tid) * 4, src + (i * 128 + tid) * 4);
}

// ---------- acc: 8 rows x 8 cols per lane = 32 f32x2 ----------
__device__ __forceinline__ void acc_zero(ull acc[32]) {
#pragma unroll
    for (int i = 0; i < 32; ++i) acc[i] = 0ULL;
}
__device__ __forceinline__ void acc_bias(ull acc[32], const float* __restrict__ b,
                                         int c0, int c1) {
    float4 b0 = *reinterpret_cast<const float4*>(b + c0);
    float4 b1 = *reinterpret_cast<const float4*>(b + c1);
    ull p0 = pk2(b0.x, b0.y), p1 = pk2(b0.z, b0.w);
    ull p2 = pk2(b1.x, b1.y), p3 = pk2(b1.z, b1.w);
#pragma unroll
    for (int r = 0; r < 8; ++r) {
        acc[r * 4 + 0] = p0; acc[r * 4 + 1] = p1;
        acc[r * 4 + 2] = p2; acc[r * 4 + 3] = p3;
    }
}
__device__ __forceinline__ void epi_raw(float* dst, int c0, int c1, const ull acc[32]) {
#pragma unroll
    for (int r = 0; r < 8; ++r) {
        float2 t0 = upk2(acc[r * 4 + 0]), t1 = upk2(acc[r * 4 + 1]);
        float2 t2 = upk2(acc[r * 4 + 2]), t3 = upk2(acc[r * 4 + 3]);
        *reinterpret_cast<float4*>(dst + r * 256 + c0) = make_float4(t0.x, t0.y, t1.x, t1.y);
        *reinterpret_cast<float4*>(dst + r * 256 + c1) = make_float4(t2.x, t2.y, t3.x, t3.y);
    }
}
__device__ __forceinline__ void epi_tanh(float* dst, int c0, int c1, const ull acc[32]) {
#pragma unroll
    for (int r = 0; r < 8; ++r) {
        float2 t0 = upk2(acc[r * 4 + 0]), t1 = upk2(acc[r * 4 + 1]);
        float2 t2 = upk2(acc[r * 4 + 2]), t3 = upk2(acc[r * 4 + 3]);
        *reinterpret_cast<float4*>(dst + r * 256 + c0) =
            make_float4(ftanh(t0.x), ftanh(t0.y), ftanh(t1.x), ftanh(t1.y));
        *reinterpret_cast<float4*>(dst + r * 256 + c1) =
            make_float4(ftanh(t2.x), ftanh(t2.y), ftanh(t3.x), ftanh(t3.y));
    }
}
__device__ __forceinline__ void epi_add(float* dst, int c0, int c1, const ull acc[32]) {
#pragma unroll
    for (int r = 0; r < 8; ++r) {
        float4 oA = *reinterpret_cast<const float4*>(dst + r * 256 + c0);
        float4 oB = *reinterpret_cast<const float4*>(dst + r * 256 + c1);
        float2 t0 = upk2(acc[r * 4 + 0]), t1 = upk2(acc[r * 4 + 1]);
        float2 t2 = upk2(acc[r * 4 + 2]), t3 = upk2(acc[r * 4 + 3]);
        *reinterpret_cast<float4*>(dst + r * 256 + c0) =
            make_float4(oA.x + t0.x, oA.y + t0.y, oA.z + t1.x, oA.w + t1.y);
        *reinterpret_cast<float4*>(dst + r * 256 + c1) =
            make_float4(oB.x + t2.x, oB.y + t2.y, oB.z + t3.x, oB.w + t3.y);
    }
}
__device__ __forceinline__ void epi_add_tanh(float* dst, int c0, int c1, const ull acc[32]) {
#pragma unroll
    for (int r = 0; r < 8; ++r) {
        float4 oA = *reinterpret_cast<const float4*>(dst + r * 256 + c0);
        float4 oB = *reinterpret_cast<const float4*>(dst + r * 256 + c1);
        float2 t0 = upk2(acc[r * 4 + 0]), t1 = upk2(acc[r * 4 + 1]);
        float2 t2 = upk2(acc[r * 4 + 2]), t3 = upk2(acc[r * 4 + 3]);
        *reinterpret_cast<float4*>(dst + r * 256 + c0) =
            make_float4(ftanh(oA.x + t0.x), ftanh(oA.y + t0.y),
                        ftanh(oA.z + t1.x), ftanh(oA.w + t1.y));
        *reinterpret_cast<float4*>(dst + r * 256 + c1) =
            make_float4(ftanh(oB.x + t2.x), ftanh(oB.y + t2.y),
                        ftanh(oB.z + t3.x), ftanh(oB.w + t3.y));
    }
}

// ---------- GEMM: [32 x 256] += A[32 x 256] * W[256 x 256] ----------
// 4 warps; warp = 8 rows x 256 cols; lane = 8 rows x 8 cols (c0, c1).
// A broadcast float4; W lane-distinct LDS.128 (16B lane stride, conflict-free).
// W double-buffered via cp.async 8-row chunks; 1 sync per chunk.
// pf0 == 0: caller (or the previous gemm via Wnext) already committed chunk 0.
// Wnext != nullptr: at the last chunk, prefetch Wnext's chunk 0 into buf0
// (freed by the c==31 barrier), so the next gemm starts with data in flight.
__device__ __forceinline__ void gemm256(
    ull acc[32], const float* __restrict__ sA,   // slot + r0*256
    const float* __restrict__ W,
    float* __restrict__ sW, int tid, int c0, int c1, int pf0,
    const float* __restrict__ Wnext)
{
    if (pf0) { pf8(sW, W, tid); CPCOMMIT(); }
#pragma unroll 1
    for (int c = 0; c < 32; ++c) {
        const float* Ab = sA + c * 8;
        float a0[8][4];
#pragma unroll
        for (int r = 0; r < 8; ++r)          // hoisted: S-slot read, independent of R
            *reinterpret_cast<float4*>(a0[r]) =
                *reinterpret_cast<const float4*>(Ab + r * 256);
        CPWAIT0();               // own slices of chunk c arrived
        __syncthreads();         // chunk c visible to all; compute c-1 done everywhere
        if (c + 1 < 32) {
            pf8(sW + ((c + 1) & 1) * 2048, W + (c + 1) * 2048, tid); CPCOMMIT();
        } else if (Wnext) {
            pf8(sW, Wnext, tid); CPCOMMIT();   // buf0 free; chain next GEMM's chunk 0
        }
        const float* buf = sW + (c & 1) * 2048;
#pragma unroll
        for (int kk = 0; kk < 4; ++kk) {
            const float* wrow = buf + kk * 256;
            ulonglong2 wA = *reinterpret_cast<const ulonglong2*>(wrow + c0);
            ulonglong2 wB = *reinterpret_cast<const ulonglong2*>(wrow + c1);
#pragma unroll
            for (int r = 0; r < 8; ++r) {
                ull a2 = pk2(a0[r][kk], a0[r][kk]);
                fma2(acc[r * 4 + 0], a2, wA.x);
                fma2(acc[r * 4 + 1], a2, wA.y);
                fma2(acc[r * 4 + 2], a2, wB.x);
                fma2(acc[r * 4 + 3], a2, wB.y);
            }
        }
        float a1[8][4];
#pragma unroll
        for (int r = 0; r < 8; ++r)
            *reinterpret_cast<float4*>(a1[r]) =
                *reinterpret_cast<const float4*>(Ab + r * 256 + 4);
#pragma unroll
        for (int kk = 0; kk < 4; ++kk) {
            const float* wrow = buf + (4 + kk) * 256;
            ulonglong2 wA = *reinterpret_cast<const ulonglong2*>(wrow + c0);
            ulonglong2 wB = *reinterpret_cast<const ulonglong2*>(wrow + c1);
#pragma unroll
            for (int r = 0; r < 8; ++r) {
                ull a2 = pk2(a1[r][kk], a1[r][kk]);
                fma2(acc[r * 4 + 0], a2, wA.x);
                fma2(acc[r * 4 + 1], a2, wA.y);
                fma2(acc[r * 4 + 2], a2, wB.x);
                fma2(acc[r * 4 + 3], a2, wB.y);
            }
        }
    }
}

// ---------- entity weight staging via cp.async (R is 4096 floats; max 3584) ----
// Caller syncs BEFORE (R buffers idle, no groups outstanding) and AFTER.
__device__ __forceinline__ void load_ent(float* __restrict__ sEnt,
    const float* __restrict__ W, const float* __restrict__ b, int F, int tid)
{
    const int total = F * 256;
    for (int i = tid * 4; i < total; i += NTHREADS * 4)
        cpa16(sEnt + i, W + i);
    if (tid < 64) cpa16(sEnt + total + tid * 4, b + tid * 4);
    CPCOMMIT();
    CPWAIT0();     // own slices landed; barrier after call publishes to all
}

// ---------- attention: warp owns 8 rows (two 4-row batches), online softmax ----------
// beta is warp-uniform after the butterfly reduction -> the max-update branch
// is warp-uniform: common path (beta <= m) skips one __expf and the v-rescale.
template<int N, int F>
__device__ __forceinline__ void attend(
    const float* __restrict__ gRow,    // gIn + (row0+r0)*OBS + off
    const float* __restrict__ sEnt,    // W (F x 256) then b (256)
    float* __restrict__ sV,            // S1 + r0*256 : q in, vi out
    int c0, int c1)
{
    float4 bA = *reinterpret_cast<const float4*>(sEnt + F * 256 + c0);
    float4 bB = *reinterpret_cast<const float4*>(sEnt + F * 256 + c1);
    ull bb0 = pk2(bA.x, bA.y), bb1 = pk2(bA.z, bA.w);
    ull bb2 = pk2(bB.x, bB.y), bb3 = pk2(bB.z, bB.w);

#pragma unroll 1
    for (int half = 0; half < 2; ++half) {
        const float* fR = gRow + half * 4 * OBS;
        float* sVr = sV + half * 4 * 256;

        float q[4][8];
#pragma unroll
        for (int r = 0; r < 4; ++r) {
            float4 qA = *reinterpret_cast<const float4*>(sVr + r * 256 + c0);
            float4 qB = *reinterpret_cast<const float4*>(sVr + r * 256 + c1);
            q[r][0] = qA.x; q[r][1] = qA.y; q[r][2] = qA.z; q[r][3] = qA.w;
            q[r][4] = qB.x; q[r][5] = qB.y; q[r][6] = qB.z; q[r][7] = qB.w;
        }
        float m[4], s[4], v[4][8];
#pragma unroll
        for (int r = 0; r < 4; ++r) {
            m[r] = -3.0e38f; s[r] = 0.0f;
#pragma unroll
            for (int i = 0; i < 8; ++i) v[r][i] = 0.0f;
        }

#pragma unroll 1
        for (int n = 0; n < N; ++n) {
            ull e0[4], e1[4], e2[4], e3[4];
#pragma unroll
            for (int r = 0; r < 4; ++r) { e0[r] = bb0; e1[r] = bb1; e2[r] = bb2; e3[r] = bb3; }
            const float* fp = fR + n * F;
#pragma unroll
            for (int j = 0; j < F; ++j) {
                ulonglong2 wA = *reinterpret_cast<const ulonglong2*>(sEnt + j * 256 + c0);
                ulonglong2 wB = *reinterpret_cast<const ulonglong2*>(sEnt + j * 256 + c1);
#pragma unroll
                for (int r = 0; r < 4; ++r) {
                    float fv = fp[r * OBS + j];          // global broadcast load
                    ull f2 = pk2(fv, fv);
                    fma2(e0[r], f2, wA.x); fma2(e1[r], f2, wA.y);
                    fma2(e2[r], f2, wB.x); fma2(e3[r], f2, wB.y);
                }
            }
#pragma unroll
            for (int r = 0; r < 4; ++r) {
                float ee[8];
                float2 t;
                t = upk2(e0[r]); ee[0] = ftanh_fast(t.x); ee[1] = ftanh_fast(t.y);
                t = upk2(e1[r]); ee[2] = ftanh_fast(t.x); ee[3] = ftanh_fast(t.y);
                t = upk2(e2[r]); ee[4] = ftanh_fast(t.x); ee[5] = ftanh_fast(t.y);
                t = upk2(e3[r]); ee[6] = ftanh_fast(t.x); ee[7] = ftanh_fast(t.y);

                float beta = q[r][0] * ee[0] + q[r][1] * ee[1] + q[r][2] * ee[2] + q[r][3] * ee[3]
                           + q[r][4] * ee[4] + q[r][5] * ee[5] + q[r][6] * ee[6] + q[r][7] * ee[7];
#pragma unroll
                for (int sh = 16; sh > 0; sh >>= 1)
                    beta += __shfl_xor_sync(0xffffffffu, beta, sh);

                if (beta <= m[r]) {                    // warp-uniform, common case
                    float wt = __expf(beta - m[r]);
                    s[r] += wt;
#pragma unroll
                    for (int i = 0; i < 8; ++i) v[r][i] = fmaf(wt, ee[i], v[r][i]);
                } else {                               // new max: rescale history
                    float sc = __expf(m[r] - beta);    // exp(-inf)=0 on first entity
                    s[r] = fmaf(s[r], sc, 1.0f);
#pragma unroll
                    for (int i = 0; i < 8; ++i) v[r][i] = fmaf(v[r][i], sc, ee[i]);
                    m[r] = beta;
                }
            }
        }
#pragma unroll
        for (int r = 0; r < 4; ++r) {
            float inv = __fdividef(1.0f, s[r]);
            *reinterpret_cast<float4*>(sVr + r * 256 + c0) =
                make_float4(v[r][0] * inv, v[r][1] * inv, v[r][2] * inv, v[r][3] * inv);
            *reinterpret_cast<float4*>(sVr + r * 256 + c1) =
                make_float4(v[r][4] * inv, v[r][5] * inv, v[r][6] * inv, v[r][7] * inv);
        }
    }
}

// Shared memory per block (floats):
//  S0 @ 0     : 32*256 = 8192  (emb_self)
//  S1 @ 8192  : 8192           (gi -> q0/vi0 -> q1/vi1 -> q2/vi2)
//  S2 @ 16384 : 8192           (h accumulator -> h)
//  R  @ 24576 : 4096           (GEMM double buffer 2x2048, OVERLAID with entity W+b)
// total 28672 floats = 114688 bytes; 2 blocks/SM = 229376 <= 233472
#define SMEM_FLOATS 28672
#define SMEM_BYTES  (SMEM_FLOATS * 4)

__global__ void __launch_bounds__(NTHREADS, 2)
obs_encoder_kernel(
    const float* __restrict__ gIn,
    const float* __restrict__ W_self,  const float* __restrict__ b_self,
    const float* __restrict__ W_other, const float* __restrict__ b_other,
    const float* __restrict__ W_box,   const float* __restrict__ b_box,
    const float* __restrict__ W_ramp,  const float* __restrict__ b_ramp,
    const float* __restrict__ corr_other, const float* __restrict__ corr_box,
    const float* __restrict__ corr_ramp,
    const float* __restrict__ W_fc, const float* __restrict__ b_fc,
    const float* __restrict__ W_e1, const float* __restrict__ b_e1,
    const float* __restrict__ W_e2, const float* __restrict__ b_e2,
    float* __restrict__ out)
{
    extern __shared__ float sm[];
    float* S0 = sm;
    float* S1 = sm + 8192;
    float* S2 = sm + 16384;
    float* R  = sm + 24576;      // GEMM W double buffer / entity weights (time-shared)

    const int tid  = threadIdx.x;
    const int lane = tid & 31;
    const int w    = tid >> 5;            // 0..3
    const int r0   = w * 8;               // warp's 8 block-local rows
    const int c0   = lane * 4, c1 = c0 + 128;
    const size_t row0 = (size_t)blockIdx.x * TB;

    const float* gRow = gIn + (row0 + r0) * OBS;

    ull acc[32];

    // G1 chunk 0 streams in underneath P1 compute
    pf8(R, W_fc, tid);
    CPCOMMIT();

    // ---- P1: emb_self = tanh(self_in @ W_self + b_self), K=10, A from global ----
    acc_bias(acc, b_self, c0, c1);
#pragma unroll
    for (int k = 0; k < 10; ++k) {
        ulonglong2 wA = *reinterpret_cast<const ulonglong2*>(W_self + k * 256 + c0);
        ulonglong2 wB = *reinterpret_cast<const ulonglong2*>(W_self + k * 256 + c1);
#pragma unroll
        for (int r = 0; r < 8; ++r) {
            float av = gRow[r * OBS + k];
            ull a2 = pk2(av, av);
            fma2(acc[r * 4 + 0], a2, wA.x); fma2(acc[r * 4 + 1], a2, wA.y);
            fma2(acc[r * 4 + 2], a2, wB.x); fma2(acc[r * 4 + 3], a2, wB.y);
        }
    }
    epi_tanh(S0 + r0 * 256, c0, c1, acc);
    // S-slot rows are warp-local; gemm's internal sync orders cross-warp state

    // ---- G1: gi = tanh(emb @ W_fc + b_fc) -> S1 ----
    acc_bias(acc, b_fc, c0, c1);
    gemm256(acc, S0 + r0 * 256, W_fc, R, tid, c0, c1, 0, W_e1);
    epi_tanh(S1 + r0 * 256, c0, c1, acc);

    // ---- G2: h = gi @ W_e1[0:256] + b_e1 -> S2 (raw) ----
    acc_bias(acc, b_e1, c0, c1);
    gemm256(acc, S1 + r0 * 256, W_e1, R, tid, c0, c1, 0, corr_other);
    epi_raw(S2 + r0 * 256, c0, c1, acc);

    // ---- G3: q_other -> S1 ; attend other ; h += vi_o @ W_e1[256:512] ----
    acc_zero(acc);
    gemm256(acc, S0 + r0 * 256, corr_other, R, tid, c0, c1, 0, nullptr);
    epi_raw(S1 + r0 * 256, c0, c1, acc);

    __syncthreads();                           // stragglers done with R; q visible
    load_ent(R, W_other, b_other, 10, tid);
    __syncthreads();                           // sEnt staged
    attend<15, 10>(gRow + 10, R, S1 + r0 * 256, c0, c1);
    __syncthreads();                           // attend reads done before gemm reuses R

    acc_zero(acc);
    gemm256(acc, S1 + r0 * 256, W_e1 + 65536, R, tid, c0, c1, 1, corr_box);
    epi_add(S2 + r0 * 256, c0, c1, acc);

    // ---- G4: q_box -> S1 ; attend box ; h += vi_b @ W_e1[512:768] ----
    acc_zero(acc);
    gemm256(acc, S0 + r0 * 256, corr_box, R, tid, c0, c1, 0, nullptr);
    epi_raw(S1 + r0 * 256, c0, c1, acc);

    __syncthreads();
    load_ent(R, W_box, b_box, 13, tid);
    __syncthreads();
    attend<16, 13>(gRow + 160, R, S1 + r0 * 256, c0, c1);
    __syncthreads();

    acc_zero(acc);
    gemm256(acc, S1 + r0 * 256, W_e1 + 131072, R, tid, c0, c1, 1, corr_ramp);
    epi_add(S2 + r0 * 256, c0, c1, acc);

    // ---- G5: q_ramp -> S1 ; attend ramp ; h = tanh(h + vi_r @ W_e1[768:1024]) ----
    acc_zero(acc);
    gemm256(acc, S0 + r0 * 256, corr_ramp, R, tid, c0, c1, 0, nullptr);
    epi_raw(S1 + r0 * 256, c0, c1, acc);

    __syncthreads();
    load_ent(R, W_ramp, b_ramp, 12, tid);
    __syncthreads();
    attend<8, 12>(gRow + 368, R, S1 + r0 * 256, c0, c1);
    __syncthreads();

    acc_zero(acc);
    gemm256(acc, S1 + r0 * 256, W_e1 + 196608, R, tid, c0, c1, 1, W_e2);
    epi_add_tanh(S2 + r0 * 256, c0, c1, acc);

    // ---- G6: out = tanh(h @ W_e2 + b_e2) -> global (coalesced float4) ----
    acc_bias(acc, b_e2, c0, c1);
    gemm256(acc, S2 + r0 * 256, W_e2, R, tid, c0, c1, 0, nullptr);
    {
        float* gdst = out + (row0 + r0) * 256;
#pragma unroll
        for (int r = 0; r < 8; ++r) {
            float2 t0 = upk2(acc[r * 4 + 0]), t1 = upk2(acc[r * 4 + 1]);
            float2 t2 = upk2(acc[r * 4 + 2]), t3 = upk2(acc[r * 4 + 3]);
            *reinterpret_cast<float4*>(gdst + r * 256 + c0) =
                make_float4(ftanh(t0.x), ftanh(t0.y), ftanh(t1.x), ftanh(t1.y));
            *reinterpret_cast<float4*>(gdst + r * 256 + c1) =
                make_float4(ftanh(t2.x), ftanh(t2.y), ftanh(t3.x), ftanh(t3.y));
        }
    }
}

extern "C" void kernel_launch(void* const* d_in, const int* in_sizes, int n_in,
                              void* d_out, int out_size) {
    const float* inputs     = (const float*)d_in[0];
    const float* W_self     = (const float*)d_in[1];
    const float* b_self     = (const float*)d_in[2];
    const float* W_other    = (const float*)d_in[3];
    const float* b_other    = (const float*)d_in[4];
    const float* W_box      = (const float*)d_in[5];
    const float* b_box      = (const float*)d_in[6];
    const float* W_ramp     = (const float*)d_in[7];
    const float* b_ramp     = (const float*)d_in[8];
    const float* corr_other = (const float*)d_in[9];
    const float* corr_box   = (const float*)d_in[10];
    const float* corr_ramp  = (const float*)d_in[11];
    const float* W_fc       = (const float*)d_in[12];
    const float* b_fc       = (const float*)d_in[13];
    const float* W_e1       = (const float*)d_in[14];
    const float* b_e1       = (const float*)d_in[15];
    const float* W_e2       = (const float*)d_in[16];
    const float* b_e2       = (const float*)d_in[17];
    float* out = (float*)d_out;

    const int B = in_sizes[0] / OBS;       // 32768
    const int nblocks = B / TB;            // 1024

    cudaFuncSetAttribute(obs_encoder_kernel,
                         cudaFuncAttributeMaxDynamicSharedMemorySize, SMEM_BYTES);

    obs_encoder_kernel<<<nblocks, NTHREADS, SMEM_BYTES>>>(
        inputs, W_self, b_self, W_other, b_other, W_box, b_box, W_ramp, b_ramp,
        corr_other, corr_box, corr_ramp, W_fc, b_fc, W_e1, b_e1, W_e2, b_e2, out);
}

// round 15
// speedup vs baseline: 1.0893x; 1.0893x over previous
#include <cuda_runtime.h>

#define TB        32
#define NTHREADS  128
#define OBS       464

typedef unsigned long long ull;

// ---------- f32x2 helpers ----------
__device__ __forceinline__ ull pk2(float lo, float hi) {
    ull r; asm("mov.b64 %0, {%1, %2};" : "=l"(r) : "f"(lo), "f"(hi)); return r;
}
__device__ __forceinline__ float2 upk2(ull v) {
    float2 f; asm("mov.b64 {%0, %1}, %2;" : "=f"(f.x), "=f"(f.y) : "l"(v)); return f;
}
__device__ __forceinline__ void fma2(ull& d, ull a, ull b) {
    asm("fma.rn.f32x2 %0, %1, %2, %0;" : "+l"(d) : "l"(a), "l"(b));
}

// exact-ish tanh: 1 - 2/(exp(2x)+1), ~1e-6 rel err (2 MUFU ops)
__device__ __forceinline__ float ftanh(float x) {
    float e = __expf(x + x);
    return 1.0f - __fdividef(2.0f, e + 1.0f);
}
// HW tanh (1 MUFU op) — attention embeddings only
__device__ __forceinline__ float ftanh_fast(float x) {
    float y; asm("tanh.approx.f32 %0, %1;" : "=f"(y) : "f"(x)); return y;
}

// ---------- cp.async ----------
__device__ __forceinline__ void cpa16(void* s, const void* g) {
    unsigned sa = (unsigned)__cvta_generic_to_shared(s);
    asm volatile("cp.async.cg.shared.global [%0], [%1], 16;" :: "r"(sa), "l"(g));
}
#define CPCOMMIT() asm volatile("cp.async.commit_group;")
#define CPWAIT0()  asm volatile("cp.async.wait_group 0;")

// prefetch one 8x256 W chunk (2048 floats) into smem (128 threads: 4 x 16B each)
__device__ __forceinline__ void pf8(float* dst, const float* src, int tid) {
#pragma unroll
    for (int i = 0; i < 4; ++i)
        cpa16(dst + (i * 128 + tid) * 4, src + (i * 128 + tid) * 4);
}

// ---------- acc: 8 rows x 8 cols per lane = 32 f32x2 ----------
__device__ __forceinline__ void acc_zero(ull acc[32]) {
#pragma unroll
    for (int i = 0; i < 32; ++i) acc[i] = 0ULL;
}
__device__ __forceinline__ void acc_bias(ull acc[32], const float* __restrict__ b,
                                         int c0, int c1) {
    float4 b0 = *reinterpret_cast<const float4*>(b + c0);
    float4 b1 = *reinterpret_cast<const float4*>(b + c1);
    ull p0 = pk2(b0.x, b0.y), p1 = pk2(b0.z, b0.w);
    ull p2 = pk2(b1.x, b1.y), p3 = pk2(b1.z, b1.w);
#pragma unroll
    for (int r = 0; r < 8; ++r) {
        acc[r * 4 + 0] = p0; acc[r * 4 + 1] = p1;
        acc[r * 4 + 2] = p2; acc[r * 4 + 3] = p3;
    }
}
__device__ __forceinline__ void epi_raw(float* dst, int c0, int c1, const ull acc[32]) {
#pragma unroll
    for (int r = 0; r < 8; ++r) {
        float2 t0 = upk2(acc[r * 4 + 0]), t1 = upk2(acc[r * 4 + 1]);
        float2 t2 = upk2(acc[r * 4 + 2]), t3 = upk2(acc[r * 4 + 3]);
        *reinterpret_cast<float4*>(dst + r * 256 + c0) = make_float4(t0.x, t0.y, t1.x, t1.y);
        *reinterpret_cast<float4*>(dst + r * 256 + c1) = make_float4(t2.x, t2.y, t3.x, t3.y);
    }
}
__device__ __forceinline__ void epi_tanh(float* dst, int c0, int c1, const ull acc[32]) {
#pragma unroll
    for (int r = 0; r < 8; ++r) {
        float2 t0 = upk2(acc[r * 4 + 0]), t1 = upk2(acc[r * 4 + 1]);
        float2 t2 = upk2(acc[r * 4 + 2]), t3 = upk2(acc[r * 4 + 3]);
        *reinterpret_cast<float4*>(dst + r * 256 + c0) =
            make_float4(ftanh(t0.x), ftanh(t0.y), ftanh(t1.x), ftanh(t1.y));
        *reinterpret_cast<float4*>(dst + r * 256 + c1) =
            make_float4(ftanh(t2.x), ftanh(t2.y), ftanh(t3.x), ftanh(t3.y));
    }
}
__device__ __forceinline__ void epi_add(float* dst, int c0, int c1, const ull acc[32]) {
#pragma unroll
    for (int r = 0; r < 8; ++r) {
        float4 oA = *reinterpret_cast<const float4*>(dst + r * 256 + c0);
        float4 oB = *reinterpret_cast<const float4*>(dst + r * 256 + c1);
        float2 t0 = upk2(acc[r * 4 + 0]), t1 = upk2(acc[r * 4 + 1]);
        float2 t2 = upk2(acc[r * 4 + 2]), t3 = upk2(acc[r * 4 + 3]);
        *reinterpret_cast<float4*>(dst + r * 256 + c0) =
            make_float4(oA.x + t0.x, oA.y + t0.y, oA.z + t1.x, oA.w + t1.y);
        *reinterpret_cast<float4*>(dst + r * 256 + c1) =
            make_float4(oB.x + t2.x, oB.y + t2.y, oB.z + t3.x, oB.w + t3.y);
    }
}
__device__ __forceinline__ void epi_add_tanh(float* dst, int c0, int c1, const ull acc[32]) {
#pragma unroll
    for (int r = 0; r < 8; ++r) {
        float4 oA = *reinterpret_cast<const float4*>(dst + r * 256 + c0);
        float4 oB = *reinterpret_cast<const float4*>(dst + r * 256 + c1);
        float2 t0 = upk2(acc[r * 4 + 0]), t1 = upk2(acc[r * 4 + 1]);
        float2 t2 = upk2(acc[r * 4 + 2]), t3 = upk2(acc[r * 4 + 3]);
        *reinterpret_cast<float4*>(dst + r * 256 + c0) =
            make_float4(ftanh(oA.x + t0.x), ftanh(oA.y + t0.y),
                        ftanh(oA.z + t1.x), ftanh(oA.w + t1.y));
        *reinterpret_cast<float4*>(dst + r * 256 + c1) =
            make_float4(ftanh(oB.x + t2.x), ftanh(oB.y + t2.y),
                        ftanh(oB.z + t3.x), ftanh(oB.w + t3.y));
    }
}

// ---------- GEMM: [32 x 256] += A[32 x 256] * W[256 x 256] ----------
// 4 warps; warp = 8 rows x 256 cols; lane = 8 rows x 8 cols (c0, c1).
// A broadcast float4; W lane-distinct LDS.128 (16B lane stride, conflict-free).
// W double-buffered via cp.async 8-row chunks; 1 sync per chunk.
// pf0 == 0: caller (or the previous gemm via Wnext) already committed chunk 0.
// Wnext != nullptr: at the last chunk, prefetch Wnext's chunk 0 into buf0
// (freed by the c==31 barrier), so the next gemm starts with data in flight.
__device__ __forceinline__ void gemm256(
    ull acc[32], const float* __restrict__ sA,   // slot + r0*256
    const float* __restrict__ W,
    float* __restrict__ sW, int tid, int c0, int c1, int pf0,
    const float* __restrict__ Wnext)
{
    if (pf0) { pf8(sW, W, tid); CPCOMMIT(); }
#pragma unroll 1
    for (int c = 0; c < 32; ++c) {
        const float* Ab = sA + c * 8;
        float a0[8][4];
#pragma unroll
        for (int r = 0; r < 8; ++r)          // hoisted: S-slot read, independent of R
            *reinterpret_cast<float4*>(a0[r]) =
                *reinterpret_cast<const float4*>(Ab + r * 256);
        CPWAIT0();               // own slices of chunk c arrived
        __syncthreads();         // chunk c visible to all; compute c-1 done everywhere
        if (c + 1 < 32) {
            pf8(sW + ((c + 1) & 1) * 2048, W + (c + 1) * 2048, tid); CPCOMMIT();
        } else if (Wnext) {
            pf8(sW, Wnext, tid); CPCOMMIT();   // buf0 free; chain next GEMM's chunk 0
        }
        const float* buf = sW + (c & 1) * 2048;
#pragma unroll
        for (int kk = 0; kk < 4; ++kk) {
            const float* wrow = buf + kk * 256;
            ulonglong2 wA = *reinterpret_cast<const ulonglong2*>(wrow + c0);
            ulonglong2 wB = *reinterpret_cast<const ulonglong2*>(wrow + c1);
#pragma unroll
            for (int r = 0; r < 8; ++r) {
                ull a2 = pk2(a0[r][kk], a0[r][kk]);
                fma2(acc[r * 4 + 0], a2, wA.x);
                fma2(acc[r * 4 + 1], a2, wA.y);
                fma2(acc[r * 4 + 2], a2, wB.x);
                fma2(acc[r * 4 + 3], a2, wB.y);
            }
        }
        float a1[8][4];
#pragma unroll
        for (int r = 0; r < 8; ++r)
            *reinterpret_cast<float4*>(a1[r]) =
                *reinterpret_cast<const float4*>(Ab + r * 256 + 4);
#pragma unroll
        for (int kk = 0; kk < 4; ++kk) {
            const float* wrow = buf + (4 + kk) * 256;
            ulonglong2 wA = *reinterpret_cast<const ulonglong2*>(wrow + c0);
            ulonglong2 wB = *reinterpret_cast<const ulonglong2*>(wrow + c1);
#pragma unroll
            for (int r = 0; r < 8; ++r) {
                ull a2 = pk2(a1[r][kk], a1[r][kk]);
                fma2(acc[r * 4 + 0], a2, wA.x);
                fma2(acc[r * 4 + 1], a2, wA.y);
                fma2(acc[r * 4 + 2], a2, wB.x);
                fma2(acc[r * 4 + 3], a2, wB.y);
            }
        }
    }
}

// ---------- entity weight staging via cp.async (R is 4096 floats; max 3584) ----
// Caller syncs BEFORE (R buffers idle, no groups outstanding) and AFTER.
__device__ __forceinline__ void load_ent(float* __restrict__ sEnt,
    const float* __restrict__ W, const float* __restrict__ b, int F, int tid)
{
    const int total = F * 256;
    for (int i = tid * 4; i < total; i += NTHREADS * 4)
        cpa16(sEnt + i, W + i);
    if (tid < 64) cpa16(sEnt + total + tid * 4, b + tid * 4);
    CPCOMMIT();
    CPWAIT0();     // own slices landed; barrier after call publishes to all
}

// ---------- attention: warp owns 8 rows (two 4-row batches), online softmax ----------
// (branchless update — R13 form; the R14 warp-uniform branch regressed)
template<int N, int F>
__device__ __forceinline__ void attend(
    const float* __restrict__ gRow,    // gIn + (row0+r0)*OBS + off
    const float* __restrict__ sEnt,    // W (F x 256) then b (256)
    float* __restrict__ sV,            // S1 + r0*256 : q in, vi out
    int c0, int c1)
{
    float4 bA = *reinterpret_cast<const float4*>(sEnt + F * 256 + c0);
    float4 bB = *reinterpret_cast<const float4*>(sEnt + F * 256 + c1);
    ull bb0 = pk2(bA.x, bA.y), bb1 = pk2(bA.z, bA.w);
    ull bb2 = pk2(bB.x, bB.y), bb3 = pk2(bB.z, bB.w);

#pragma unroll 1
    for (int half = 0; half < 2; ++half) {
        const float* fR = gRow + half * 4 * OBS;
        float* sVr = sV + half * 4 * 256;

        float q[4][8];
#pragma unroll
        for (int r = 0; r < 4; ++r) {
            float4 qA = *reinterpret_cast<const float4*>(sVr + r * 256 + c0);
            float4 qB = *reinterpret_cast<const float4*>(sVr + r * 256 + c1);
            q[r][0] = qA.x; q[r][1] = qA.y; q[r][2] = qA.z; q[r][3] = qA.w;
            q[r][4] = qB.x; q[r][5] = qB.y; q[r][6] = qB.z; q[r][7] = qB.w;
        }
        float m[4], s[4], v[4][8];
#pragma unroll
        for (int r = 0; r < 4; ++r) {
            m[r] = -3.0e38f; s[r] = 0.0f;
#pragma unroll
            for (int i = 0; i < 8; ++i) v[r][i] = 0.0f;
        }

#pragma unroll 1
        for (int n = 0; n < N; ++n) {
            ull e0[4], e1[4], e2[4], e3[4];
#pragma unroll
            for (int r = 0; r < 4; ++r) { e0[r] = bb0; e1[r] = bb1; e2[r] = bb2; e3[r] = bb3; }
            const float* fp = fR + n * F;
#pragma unroll
            for (int j = 0; j < F; ++j) {
                ulonglong2 wA = *reinterpret_cast<const ulonglong2*>(sEnt + j * 256 + c0);
                ulonglong2 wB = *reinterpret_cast<const ulonglong2*>(sEnt + j * 256 + c1);
#pragma unroll
                for (int r = 0; r < 4; ++r) {
                    float fv = fp[r * OBS + j];          // global broadcast load
                    ull f2 = pk2(fv, fv);
                    fma2(e0[r], f2, wA.x); fma2(e1[r], f2, wA.y);
                    fma2(e2[r], f2, wB.x); fma2(e3[r], f2, wB.y);
                }
            }
#pragma unroll
            for (int r = 0; r < 4; ++r) {
                float ee[8];
                float2 t;
                t = upk2(e0[r]); ee[0] = ftanh_fast(t.x); ee[1] = ftanh_fast(t.y);
                t = upk2(e1[r]); ee[2] = ftanh_fast(t.x); ee[3] = ftanh_fast(t.y);
                t = upk2(e2[r]); ee[4] = ftanh_fast(t.x); ee[5] = ftanh_fast(t.y);
                t = upk2(e3[r]); ee[6] = ftanh_fast(t.x); ee[7] = ftanh_fast(t.y);

                float beta = q[r][0] * ee[0] + q[r][1] * ee[1] + q[r][2] * ee[2] + q[r][3] * ee[3]
                           + q[r][4] * ee[4] + q[r][5] * ee[5] + q[r][6] * ee[6] + q[r][7] * ee[7];
#pragma unroll
                for (int sh = 16; sh > 0; sh >>= 1)
                    beta += __shfl_xor_sync(0xffffffffu, beta, sh);

                float mn = fmaxf(m[r], beta);
                float sc = __expf(m[r] - mn);    // 0 on first entity
                float wt = __expf(beta - mn);
                s[r] = s[r] * sc + wt;
#pragma unroll
                for (int i = 0; i < 8; ++i) v[r][i] = v[r][i] * sc + wt * ee[i];
                m[r] = mn;
            }
        }
#pragma unroll
        for (int r = 0; r < 4; ++r) {
            float inv = __fdividef(1.0f, s[r]);
            *reinterpret_cast<float4*>(sVr + r * 256 + c0) =
                make_float4(v[r][0] * inv, v[r][1] * inv, v[r][2] * inv, v[r][3] * inv);
            *reinterpret_cast<float4*>(sVr + r * 256 + c1) =
                make_float4(v[r][4] * inv, v[r][5] * inv, v[r][6] * inv, v[r][7] * inv);
        }
    }
}

// Shared memory per block (floats):
//  S0 @ 0     : 32*256 = 8192  (emb_self)
//  S1 @ 8192  : 8192           (gi -> q0/vi0 -> q1/vi1 -> q2/vi2)
//  S2 @ 16384 : 8192           (h accumulator -> h)
//  R  @ 24576 : 4096           (GEMM double buffer 2x2048, OVERLAID with entity W+b)
// total 28672 floats = 114688 bytes; 2 blocks/SM = 229376 <= 233472
#define SMEM_FLOATS 28672
#define SMEM_BYTES  (SMEM_FLOATS * 4)

__global__ void __launch_bounds__(NTHREADS, 2)
obs_encoder_kernel(
    const float* __restrict__ gIn,
    const float* __restrict__ W_self,  const float* __restrict__ b_self,
    const float* __restrict__ W_other, const float* __restrict__ b_other,
    const float* __restrict__ W_box,   const float* __restrict__ b_box,
    const float* __restrict__ W_ramp,  const float* __restrict__ b_ramp,
    const float* __restrict__ corr_other, const float* __restrict__ corr_box,
    const float* __restrict__ corr_ramp,
    const float* __restrict__ W_fc, const float* __restrict__ b_fc,
    const float* __restrict__ W_e1, const float* __restrict__ b_e1,
    const float* __restrict__ W_e2, const float* __restrict__ b_e2,
    float* __restrict__ out)
{
    extern __shared__ float sm[];
    float* S0 = sm;
    float* S1 = sm + 8192;
    float* S2 = sm + 16384;
    float* R  = sm + 24576;      // GEMM W double buffer / entity weights (time-shared)

    const int tid  = threadIdx.x;
    const int lane = tid & 31;
    const int w    = tid >> 5;            // 0..3
    const int r0   = w * 8;               // warp's 8 block-local rows
    const int c0   = lane * 4, c1 = c0 + 128;
    const size_t row0 = (size_t)blockIdx.x * TB;

    const float* gRow = gIn + (row0 + r0) * OBS;

    ull acc[32];

    // G1 chunk 0 streams in underneath P1 compute
    pf8(R, W_fc, tid);
    CPCOMMIT();

    // ---- P1: emb_self = tanh(self_in @ W_self + b_self), K=10, A from global ----
    acc_bias(acc, b_self, c0, c1);
#pragma unroll
    for (int k = 0; k < 10; ++k) {
        ulonglong2 wA = *reinterpret_cast<const ulonglong2*>(W_self + k * 256 + c0);
        ulonglong2 wB = *reinterpret_cast<const ulonglong2*>(W_self + k * 256 + c1);
#pragma unroll
        for (int r = 0; r < 8; ++r) {
            float av = gRow[r * OBS + k];
            ull a2 = pk2(av, av);
            fma2(acc[r * 4 + 0], a2, wA.x); fma2(acc[r * 4 + 1], a2, wA.y);
            fma2(acc[r * 4 + 2], a2, wB.x); fma2(acc[r * 4 + 3], a2, wB.y);
        }
    }
    epi_tanh(S0 + r0 * 256, c0, c1, acc);
    // S-slot rows are warp-local; gemm's internal sync orders cross-warp state

    // ---- G1: gi = tanh(emb @ W_fc + b_fc) -> S1 ----
    acc_bias(acc, b_fc, c0, c1);
    gemm256(acc, S0 + r0 * 256, W_fc, R, tid, c0, c1, 0, W_e1);
    epi_tanh(S1 + r0 * 256, c0, c1, acc);

    // ---- G2: h = gi @ W_e1[0:256] + b_e1 -> S2 (raw) ----
    acc_bias(acc, b_e1, c0, c1);
    gemm256(acc, S1 + r0 * 256, W_e1, R, tid, c0, c1, 0, corr_other);
    epi_raw(S2 + r0 * 256, c0, c1, acc);

    // ---- G3: q_other -> S1 ; attend other ; h += vi_o @ W_e1[256:512] ----
    acc_zero(acc);
    gemm256(acc, S0 + r0 * 256, corr_other, R, tid, c0, c1, 0, nullptr);
    epi_raw(S1 + r0 * 256, c0, c1, acc);

    __syncthreads();                           // stragglers done with R; q visible
    load_ent(R, W_other, b_other, 10, tid);
    __syncthreads();                           // sEnt staged
    attend<15, 10>(gRow + 10, R, S1 + r0 * 256, c0, c1);
    __syncthreads();                           // attend reads done before gemm reuses R

    acc_zero(acc);
    gemm256(acc, S1 + r0 * 256, W_e1 + 65536, R, tid, c0, c1, 1, corr_box);
    epi_add(S2 + r0 * 256, c0, c1, acc);

    // ---- G4: q_box -> S1 ; attend box ; h += vi_b @ W_e1[512:768] ----
    acc_zero(acc);
    gemm256(acc, S0 + r0 * 256, corr_box, R, tid, c0, c1, 0, nullptr);
    epi_raw(S1 + r0 * 256, c0, c1, acc);

    __syncthreads();
    load_ent(R, W_box, b_box, 13, tid);
    __syncthreads();
    attend<16, 13>(gRow + 160, R, S1 + r0 * 256, c0, c1);
    __syncthreads();

    acc_zero(acc);
    gemm256(acc, S1 + r0 * 256, W_e1 + 131072, R, tid, c0, c1, 1, corr_ramp);
    epi_add(S2 + r0 * 256, c0, c1, acc);

    // ---- G5: q_ramp -> S1 ; attend ramp ; h = tanh(h + vi_r @ W_e1[768:1024]) ----
    acc_zero(acc);
    gemm256(acc, S0 + r0 * 256, corr_ramp, R, tid, c0, c1, 0, nullptr);
    epi_raw(S1 + r0 * 256, c0, c1, acc);

    __syncthreads();
    load_ent(R, W_ramp, b_ramp, 12, tid);
    __syncthreads();
    attend<8, 12>(gRow + 368, R, S1 + r0 * 256, c0, c1);
    __syncthreads();

    acc_zero(acc);
    gemm256(acc, S1 + r0 * 256, W_e1 + 196608, R, tid, c0, c1, 1, W_e2);
    epi_add_tanh(S2 + r0 * 256, c0, c1, acc);

    // ---- G6: out = tanh(h @ W_e2 + b_e2) -> global (coalesced float4) ----
    acc_bias(acc, b_e2, c0, c1);
    gemm256(acc, S2 + r0 * 256, W_e2, R, tid, c0, c1, 0, nullptr);
    {
        float* gdst = out + (row0 + r0) * 256;
#pragma unroll
        for (int r = 0; r < 8; ++r) {
            float2 t0 = upk2(acc[r * 4 + 0]), t1 = upk2(acc[r * 4 + 1]);
            float2 t2 = upk2(acc[r * 4 + 2]), t3 = upk2(acc[r * 4 + 3]);
            *reinterpret_cast<float4*>(gdst + r * 256 + c0) =
                make_float4(ftanh(t0.x), ftanh(t0.y), ftanh(t1.x), ftanh(t1.y));
            *reinterpret_cast<float4*>(gdst + r * 256 + c1) =
                make_float4(ftanh(t2.x), ftanh(t2.y), ftanh(t3.x), ftanh(t3.y));
        }
    }
}

extern "C" void kernel_launch(void* const* d_in, const int* in_sizes, int n_in,
                              void* d_out, int out_size) {
    const float* inputs     = (const float*)d_in[0];
    const float* W_self     = (const float*)d_in[1];
    const float* b_self     = (const float*)d_in[2];
    const float* W_other    = (const float*)d_in[3];
    const float* b_other    = (const float*)d_in[4];
    const float* W_box      = (const float*)d_in[5];
    const float* b_box      = (const float*)d_in[6];
    const float* W_ramp     = (const float*)d_in[7];
    const float* b_ramp     = (const float*)d_in[8];
    const float* corr_other = (const float*)d_in[9];
    const float* corr_box   = (const float*)d_in[10];
    const float* corr_ramp  = (const float*)d_in[11];
    const float* W_fc       = (const float*)d_in[12];
    const float* b_fc       = (const float*)d_in[13];
    const float* W_e1       = (const float*)d_in[14];
    const float* b_e1       = (const float*)d_in[15];
    const float* W_e2       = (const float*)d_in[16];
    const float* b_e2       = (const float*)d_in[17];
    float* out = (float*)d_out;

    const int B = in_sizes[0] / OBS;       // 32768
    const int nblocks = B / TB;            // 1024

    cudaFuncSetAttribute(obs_encoder_kernel,
                         cudaFuncAttributeMaxDynamicSharedMemorySize, SMEM_BYTES);

    obs_encoder_kernel<<<nblocks, NTHREADS, SMEM_BYTES>>>(
        inputs, W_self, b_self, W_other, b_other, W_box, b_box, W_ramp, b_ramp,
        corr_other, corr_box, corr_ramp, W_fc, b_fc, W_e1, b_e1, W_e2, b_e2, out);
}